// round 1
// baseline (speedup 1.0000x reference)
// MoEExperts: dense 8-expert MoE, T=4096, H=1024, Q=1024, E=8.
// Round 1: tf32 mma.sync (m16n8k8) tiled GEMMs + fused silu/routing scratch pass.
//   k1: gate_up[e] = x @ W1[e]            (per-expert GEMM, N=2048)
//   k2: hidden[t, e*Q+q] = rw[t,e]*silu(gate)*up   (elementwise)
//   k3: out = hidden(4096x8192) @ down(8192x1024)  (single GEMM)
// All fragments pass through cvt.rna.tf32 (HW truncates raw fp32 -> bias fail).

#include <cuda_runtime.h>
#include <cstdint>

#define Tt 4096
#define Ee 8
#define Hh 1024
#define Qq 1024

// Scratch (allocation-free rule: __device__ globals).
__device__ float g_gu[(size_t)Ee * Tt * 2 * Qq];     // (E, T, 2Q)  268 MB
__device__ float g_hidden[(size_t)Tt * Ee * Qq];     // (T, E*Q)    134 MB

// ---------------------------------------------------------------- helpers
__device__ __forceinline__ unsigned smem_u32(const void* p) {
    return (unsigned)__cvta_generic_to_shared(p);
}
__device__ __forceinline__ void cp_async16(unsigned s, const void* g) {
    asm volatile("cp.async.cg.shared.global [%0], [%1], 16;\n" :: "r"(s), "l"(g));
}
__device__ __forceinline__ void cp_commit() {
    asm volatile("cp.async.commit_group;\n");
}
template<int N>
__device__ __forceinline__ void cp_wait() {
    asm volatile("cp.async.wait_group %0;\n" :: "n"(N));
}
// Round-to-nearest fp32 -> tf32 (value kept in a 32-bit container, low 13 bits 0).
__device__ __forceinline__ unsigned tf32_rna(float f) {
    unsigned r;
    asm("cvt.rna.tf32.f32 %0, %1;\n" : "=r"(r) : "f"(f));
    return r;
}
__device__ __forceinline__ void mma_tf32(float* c, const unsigned* a, const unsigned* b) {
    asm volatile(
        "mma.sync.aligned.m16n8k8.row.col.f32.tf32.tf32.f32 "
        "{%0,%1,%2,%3}, {%4,%5,%6,%7}, {%8,%9}, {%0,%1,%2,%3};\n"
        : "+f"(c[0]), "+f"(c[1]), "+f"(c[2]), "+f"(c[3])
        : "r"(a[0]), "r"(a[1]), "r"(a[2]), "r"(a[3]), "r"(b[0]), "r"(b[1]));
}

// ---------------------------------------------------------------- GEMM
// C[m0:m0+128, n0:n0+128] (+z offsets) = A(MxK, lda) @ B(KxN, ldb), row-major.
// M,N multiples of 128; K multiple of 16. 256 threads, 8 warps (4m x 2n),
// warp tile 32x64 via m16n8k8 tf32. 2-stage cp.async smem pipeline.
constexpr int BM = 128, BN = 128, BK = 16;
constexpr int APAD = 4;   // A row stride 20 floats -> conflict-free frags
constexpr int BPAD = 8;   // B row stride 136 floats -> conflict-free frags

__global__ __launch_bounds__(256, 2)
void gemm_tf32(const float* __restrict__ A, int lda,
               const float* __restrict__ B, int ldb, long long sBz,
               float* __restrict__ C, int ldc, long long sCz,
               int K)
{
    __shared__ float As[2][BM][BK + APAD];  // 20 KB
    __shared__ float Bs[2][BK][BN + BPAD];  // 17 KB

    const int tid = threadIdx.x;
    const int m0 = blockIdx.y * BM;
    const int n0 = blockIdx.x * BN;

    A += (size_t)m0 * lda;
    B += (size_t)blockIdx.z * sBz + n0;
    C += (size_t)blockIdx.z * sCz + (size_t)m0 * ldc + n0;

    const int lane = tid & 31, warp = tid >> 5;
    const int wm = warp >> 1;        // 0..3 -> 32-row slab
    const int wn = warp & 1;         // 0..1 -> 64-col slab
    const int gid = lane >> 2;       // groupID (0..7)
    const int tig = lane & 3;        // thread-in-group (0..3)

    auto load_stage = [&](int it, int st) {
        const int k0 = it * BK;
        #pragma unroll
        for (int i = 0; i < 2; i++) {          // A: 128 rows x 4 x 16B
            int c = tid + i * 256;
            int m = c >> 2, j = c & 3;
            cp_async16(smem_u32(&As[st][m][j * 4]),
                       A + (size_t)m * lda + k0 + j * 4);
        }
        #pragma unroll
        for (int i = 0; i < 2; i++) {          // B: 16 rows x 32 x 16B
            int c = tid + i * 256;
            int r = c >> 5, j = c & 31;
            cp_async16(smem_u32(&Bs[st][r][j * 4]),
                       B + (size_t)(k0 + r) * ldb + j * 4);
        }
        cp_commit();
    };

    float acc[2][8][4];
    #pragma unroll
    for (int im = 0; im < 2; im++)
        #pragma unroll
        for (int in = 0; in < 8; in++)
            #pragma unroll
            for (int v = 0; v < 4; v++) acc[im][in][v] = 0.f;

    const int nIter = K / BK;
    load_stage(0, 0);

    for (int it = 0; it < nIter; ++it) {
        const int cur = it & 1;
        if (it + 1 < nIter) { load_stage(it + 1, cur ^ 1); cp_wait<1>(); }
        else                { cp_wait<0>(); }
        __syncthreads();

        #pragma unroll
        for (int kk = 0; kk < BK; kk += 8) {
            unsigned a[2][4], bf[8][2];
            #pragma unroll
            for (int im = 0; im < 2; im++) {
                const int r = wm * 32 + im * 16 + gid;
                a[im][0] = tf32_rna(As[cur][r    ][kk + tig]);
                a[im][1] = tf32_rna(As[cur][r + 8][kk + tig]);
                a[im][2] = tf32_rna(As[cur][r    ][kk + tig + 4]);
                a[im][3] = tf32_rna(As[cur][r + 8][kk + tig + 4]);
            }
            #pragma unroll
            for (int in = 0; in < 8; in++) {
                const int nb = wn * 64 + in * 8 + gid;
                bf[in][0] = tf32_rna(Bs[cur][kk + tig    ][nb]);
                bf[in][1] = tf32_rna(Bs[cur][kk + tig + 4][nb]);
            }
            #pragma unroll
            for (int im = 0; im < 2; im++)
                #pragma unroll
                for (int in = 0; in < 8; in++)
                    mma_tf32(acc[im][in], a[im], bf[in]);
        }
        __syncthreads();
    }

    // Epilogue: fp32 stores (float2 per fragment half)
    #pragma unroll
    for (int im = 0; im < 2; im++) {
        const int r = wm * 32 + im * 16 + gid;
        #pragma unroll
        for (int in = 0; in < 8; in++) {
            const int col = wn * 64 + in * 8 + 2 * tig;
            *(float2*)&C[(size_t)r * ldc + col] =
                make_float2(acc[im][in][0], acc[im][in][1]);
            *(float2*)&C[(size_t)(r + 8) * ldc + col] =
                make_float2(acc[im][in][2], acc[im][in][3]);
        }
    }
}

// ---------------------------------------------------------------- silu
// hidden[t][e*Q + q] = rw[t,e] * silu(gate)*up ; gate/up from g_gu (E,T,2Q).
__global__ void silu_mul(const float* __restrict__ gu,
                         const float* __restrict__ rw,
                         float* __restrict__ hidden)
{
    const int i = blockIdx.x * blockDim.x + threadIdx.x;  // 8,388,608 threads
    const int q4 = i & 255;                // Q/4 = 256 groups of float4
    const int t  = (i >> 8) & (Tt - 1);
    const int e  = i >> 20;                // / (256*4096)

    const size_t base = ((size_t)e * Tt + t) * (2 * Qq);
    const float4 g = *(const float4*)&gu[base + q4 * 4];
    const float4 u = *(const float4*)&gu[base + Qq + q4 * 4];
    const float w = rw[t * Ee + e];

    float4 h;
    h.x = w * u.x * (g.x / (1.f + __expf(-g.x)));
    h.y = w * u.y * (g.y / (1.f + __expf(-g.y)));
    h.z = w * u.z * (g.z / (1.f + __expf(-g.z)));
    h.w = w * u.w * (g.w / (1.f + __expf(-g.w)));

    *(float4*)&hidden[(size_t)t * (Ee * Qq) + e * Qq + q4 * 4] = h;
}

// ---------------------------------------------------------------- launch
extern "C" void kernel_launch(void* const* d_in, const int* in_sizes, int n_in,
                              void* d_out, int out_size)
{
    (void)in_sizes; (void)n_in; (void)out_size;
    const float* x    = (const float*)d_in[0];  // (T, H)
    const float* rw   = (const float*)d_in[1];  // (T, E)
    const float* gup  = (const float*)d_in[2];  // (E, H, 2Q)
    const float* down = (const float*)d_in[3];  // (E, Q, H)
    float* out = (float*)d_out;                 // (T, H)

    float *gu = nullptr, *hid = nullptr;
    cudaGetSymbolAddress((void**)&gu,  g_gu);
    cudaGetSymbolAddress((void**)&hid, g_hidden);

    // k1: per-expert gate_up GEMM: (4096 x 1024) @ (1024 x 2048) -> g_gu[e]
    dim3 g1(2 * Qq / BN, Tt / BM, Ee);   // (16, 32, 8)
    gemm_tf32<<<g1, 256>>>(x, Hh,
                           gup, 2 * Qq, (long long)Hh * 2 * Qq,
                           gu,  2 * Qq, (long long)Tt * 2 * Qq,
                           Hh);

    // k2: silu * up * routing weight -> hidden (T, E*Q)
    silu_mul<<<(Tt * Ee * Qq / 4) / 256, 256>>>(gu, rw, hid);

    // k3: (4096 x 8192) @ (8192 x 1024) -> out
    dim3 g2(Hh / BN, Tt / BM, 1);        // (8, 32)
    gemm_tf32<<<g2, 256>>>(hid, Ee * Qq,
                           down, Hh, 0,
                           out,  Hh, 0,
                           Ee * Qq);
}

// round 2
// speedup vs baseline: 1.0000x; 1.0000x over previous
// MoEExperts: dense 8-expert MoE, T=4096, H=1024, Q=1024, E=8.
// Round 1: tf32 mma.sync (m16n8k8) tiled GEMMs + fused silu/routing scratch pass.
//   k1: gate_up[e] = x @ W1[e]            (per-expert GEMM, N=2048)
//   k2: hidden[t, e*Q+q] = rw[t,e]*silu(gate)*up   (elementwise)
//   k3: out = hidden(4096x8192) @ down(8192x1024)  (single GEMM)
// All fragments pass through cvt.rna.tf32 (HW truncates raw fp32 -> bias fail).

#include <cuda_runtime.h>
#include <cstdint>

#define Tt 4096
#define Ee 8
#define Hh 1024
#define Qq 1024

// Scratch (allocation-free rule: __device__ globals).
__device__ float g_gu[(size_t)Ee * Tt * 2 * Qq];     // (E, T, 2Q)  268 MB
__device__ float g_hidden[(size_t)Tt * Ee * Qq];     // (T, E*Q)    134 MB

// ---------------------------------------------------------------- helpers
__device__ __forceinline__ unsigned smem_u32(const void* p) {
    return (unsigned)__cvta_generic_to_shared(p);
}
__device__ __forceinline__ void cp_async16(unsigned s, const void* g) {
    asm volatile("cp.async.cg.shared.global [%0], [%1], 16;\n" :: "r"(s), "l"(g));
}
__device__ __forceinline__ void cp_commit() {
    asm volatile("cp.async.commit_group;\n");
}
template<int N>
__device__ __forceinline__ void cp_wait() {
    asm volatile("cp.async.wait_group %0;\n" :: "n"(N));
}
// Round-to-nearest fp32 -> tf32 (value kept in a 32-bit container, low 13 bits 0).
__device__ __forceinline__ unsigned tf32_rna(float f) {
    unsigned r;
    asm("cvt.rna.tf32.f32 %0, %1;\n" : "=r"(r) : "f"(f));
    return r;
}
__device__ __forceinline__ void mma_tf32(float* c, const unsigned* a, const unsigned* b) {
    asm volatile(
        "mma.sync.aligned.m16n8k8.row.col.f32.tf32.tf32.f32 "
        "{%0,%1,%2,%3}, {%4,%5,%6,%7}, {%8,%9}, {%0,%1,%2,%3};\n"
        : "+f"(c[0]), "+f"(c[1]), "+f"(c[2]), "+f"(c[3])
        : "r"(a[0]), "r"(a[1]), "r"(a[2]), "r"(a[3]), "r"(b[0]), "r"(b[1]));
}

// ---------------------------------------------------------------- GEMM
// C[m0:m0+128, n0:n0+128] (+z offsets) = A(MxK, lda) @ B(KxN, ldb), row-major.
// M,N multiples of 128; K multiple of 16. 256 threads, 8 warps (4m x 2n),
// warp tile 32x64 via m16n8k8 tf32. 2-stage cp.async smem pipeline.
constexpr int BM = 128, BN = 128, BK = 16;
constexpr int APAD = 4;   // A row stride 20 floats -> conflict-free frags
constexpr int BPAD = 8;   // B row stride 136 floats -> conflict-free frags

__global__ __launch_bounds__(256, 2)
void gemm_tf32(const float* __restrict__ A, int lda,
               const float* __restrict__ B, int ldb, long long sBz,
               float* __restrict__ C, int ldc, long long sCz,
               int K)
{
    __shared__ float As[2][BM][BK + APAD];  // 20 KB
    __shared__ float Bs[2][BK][BN + BPAD];  // 17 KB

    const int tid = threadIdx.x;
    const int m0 = blockIdx.y * BM;
    const int n0 = blockIdx.x * BN;

    A += (size_t)m0 * lda;
    B += (size_t)blockIdx.z * sBz + n0;
    C += (size_t)blockIdx.z * sCz + (size_t)m0 * ldc + n0;

    const int lane = tid & 31, warp = tid >> 5;
    const int wm = warp >> 1;        // 0..3 -> 32-row slab
    const int wn = warp & 1;         // 0..1 -> 64-col slab
    const int gid = lane >> 2;       // groupID (0..7)
    const int tig = lane & 3;        // thread-in-group (0..3)

    auto load_stage = [&](int it, int st) {
        const int k0 = it * BK;
        #pragma unroll
        for (int i = 0; i < 2; i++) {          // A: 128 rows x 4 x 16B
            int c = tid + i * 256;
            int m = c >> 2, j = c & 3;
            cp_async16(smem_u32(&As[st][m][j * 4]),
                       A + (size_t)m * lda + k0 + j * 4);
        }
        #pragma unroll
        for (int i = 0; i < 2; i++) {          // B: 16 rows x 32 x 16B
            int c = tid + i * 256;
            int r = c >> 5, j = c & 31;
            cp_async16(smem_u32(&Bs[st][r][j * 4]),
                       B + (size_t)(k0 + r) * ldb + j * 4);
        }
        cp_commit();
    };

    float acc[2][8][4];
    #pragma unroll
    for (int im = 0; im < 2; im++)
        #pragma unroll
        for (int in = 0; in < 8; in++)
            #pragma unroll
            for (int v = 0; v < 4; v++) acc[im][in][v] = 0.f;

    const int nIter = K / BK;
    load_stage(0, 0);

    for (int it = 0; it < nIter; ++it) {
        const int cur = it & 1;
        if (it + 1 < nIter) { load_stage(it + 1, cur ^ 1); cp_wait<1>(); }
        else                { cp_wait<0>(); }
        __syncthreads();

        #pragma unroll
        for (int kk = 0; kk < BK; kk += 8) {
            unsigned a[2][4], bf[8][2];
            #pragma unroll
            for (int im = 0; im < 2; im++) {
                const int r = wm * 32 + im * 16 + gid;
                a[im][0] = tf32_rna(As[cur][r    ][kk + tig]);
                a[im][1] = tf32_rna(As[cur][r + 8][kk + tig]);
                a[im][2] = tf32_rna(As[cur][r    ][kk + tig + 4]);
                a[im][3] = tf32_rna(As[cur][r + 8][kk + tig + 4]);
            }
            #pragma unroll
            for (int in = 0; in < 8; in++) {
                const int nb = wn * 64 + in * 8 + gid;
                bf[in][0] = tf32_rna(Bs[cur][kk + tig    ][nb]);
                bf[in][1] = tf32_rna(Bs[cur][kk + tig + 4][nb]);
            }
            #pragma unroll
            for (int im = 0; im < 2; im++)
                #pragma unroll
                for (int in = 0; in < 8; in++)
                    mma_tf32(acc[im][in], a[im], bf[in]);
        }
        __syncthreads();
    }

    // Epilogue: fp32 stores (float2 per fragment half)
    #pragma unroll
    for (int im = 0; im < 2; im++) {
        const int r = wm * 32 + im * 16 + gid;
        #pragma unroll
        for (int in = 0; in < 8; in++) {
            const int col = wn * 64 + in * 8 + 2 * tig;
            *(float2*)&C[(size_t)r * ldc + col] =
                make_float2(acc[im][in][0], acc[im][in][1]);
            *(float2*)&C[(size_t)(r + 8) * ldc + col] =
                make_float2(acc[im][in][2], acc[im][in][3]);
        }
    }
}

// ---------------------------------------------------------------- silu
// hidden[t][e*Q + q] = rw[t,e] * silu(gate)*up ; gate/up from g_gu (E,T,2Q).
__global__ void silu_mul(const float* __restrict__ gu,
                         const float* __restrict__ rw,
                         float* __restrict__ hidden)
{
    const int i = blockIdx.x * blockDim.x + threadIdx.x;  // 8,388,608 threads
    const int q4 = i & 255;                // Q/4 = 256 groups of float4
    const int t  = (i >> 8) & (Tt - 1);
    const int e  = i >> 20;                // / (256*4096)

    const size_t base = ((size_t)e * Tt + t) * (2 * Qq);
    const float4 g = *(const float4*)&gu[base + q4 * 4];
    const float4 u = *(const float4*)&gu[base + Qq + q4 * 4];
    const float w = rw[t * Ee + e];

    float4 h;
    h.x = w * u.x * (g.x / (1.f + __expf(-g.x)));
    h.y = w * u.y * (g.y / (1.f + __expf(-g.y)));
    h.z = w * u.z * (g.z / (1.f + __expf(-g.z)));
    h.w = w * u.w * (g.w / (1.f + __expf(-g.w)));

    *(float4*)&hidden[(size_t)t * (Ee * Qq) + e * Qq + q4 * 4] = h;
}

// ---------------------------------------------------------------- launch
extern "C" void kernel_launch(void* const* d_in, const int* in_sizes, int n_in,
                              void* d_out, int out_size)
{
    (void)in_sizes; (void)n_in; (void)out_size;
    const float* x    = (const float*)d_in[0];  // (T, H)
    const float* rw   = (const float*)d_in[1];  // (T, E)
    const float* gup  = (const float*)d_in[2];  // (E, H, 2Q)
    const float* down = (const float*)d_in[3];  // (E, Q, H)
    float* out = (float*)d_out;                 // (T, H)

    float *gu = nullptr, *hid = nullptr;
    cudaGetSymbolAddress((void**)&gu,  g_gu);
    cudaGetSymbolAddress((void**)&hid, g_hidden);

    // k1: per-expert gate_up GEMM: (4096 x 1024) @ (1024 x 2048) -> g_gu[e]
    dim3 g1(2 * Qq / BN, Tt / BM, Ee);   // (16, 32, 8)
    gemm_tf32<<<g1, 256>>>(x, Hh,
                           gup, 2 * Qq, (long long)Hh * 2 * Qq,
                           gu,  2 * Qq, (long long)Tt * 2 * Qq,
                           Hh);

    // k2: silu * up * routing weight -> hidden (T, E*Q)
    silu_mul<<<(Tt * Ee * Qq / 4) / 256, 256>>>(gu, rw, hid);

    // k3: (4096 x 8192) @ (8192 x 1024) -> out
    dim3 g2(Hh / BN, Tt / BM, 1);        // (8, 32)
    gemm_tf32<<<g2, 256>>>(hid, Ee * Qq,
                           down, Hh, 0,
                           out,  Hh, 0,
                           Ee * Qq);
}